// round 10
// baseline (speedup 1.0000x reference)
#include <cuda_runtime.h>
#include <cuda_bf16.h>

// Leapfrog integrator, GM = 1, A_SCALE = 1. One thread per PARTICLE,
// integrating trail (lane lo) and lead (lane hi) together with packed
// f32x2 math (FFMA2, PTX-only on Blackwell).
//
// Force scalar 1/(r(1+r)^2 + eps) = u * g^2 per lane, u = rsqrt(s) (the only
// MUFU work: 2 scalar rsqrt per thread-step = 1 per trajectory-step).
// g = 1/(1+r) is Newton-tracked across steps (seed = previous g, TWO packed
// Newton iterations — the R6/R8 scheme, measured rel_err 2.35e-5).
// Sign handling without neg modifiers: nu = -u, nh = fma2(s,nu,-1) = -(1+r),
// cu = (+dt)*nu = -dt*u; kick = p = fma2(cu*g*g, q, p).
// Interior kicks fused: one p += dt*a per interior step.

typedef unsigned long long f2;   // packed f32x2 (lo, hi)

__device__ __forceinline__ f2 pack2(float lo, float hi) {
    f2 r; asm("mov.b64 %0, {%1, %2};" : "=l"(r) : "f"(lo), "f"(hi)); return r;
}
__device__ __forceinline__ void unpack2(f2 v, float& lo, float& hi) {
    asm("mov.b64 {%0, %1}, %2;" : "=f"(lo), "=f"(hi) : "l"(v));
}
__device__ __forceinline__ f2 fma2(f2 a, f2 b, f2 c) {
    f2 r; asm("fma.rn.f32x2 %0, %1, %2, %3;" : "=l"(r) : "l"(a), "l"(b), "l"(c)); return r;
}
__device__ __forceinline__ f2 mul2(f2 a, f2 b) {
    f2 r; asm("mul.rn.f32x2 %0, %1, %2;" : "=l"(r) : "l"(a), "l"(b)); return r;
}
__device__ __forceinline__ float rsqrt_approx(float x) {
    float y; asm("rsqrt.approx.f32 %0, %1;" : "=f"(y) : "f"(x)); return y;
}
__device__ __forceinline__ float rcp_approx(float x) {
    float y; asm("rcp.approx.f32 %0, %1;" : "=f"(y) : "f"(x)); return y;
}

struct StateP {                  // both trajectories, packed per component
    f2 qx, qy, qz, px, py, pz;
    f2 g;                        // tracked 1/(1+r) per lane
};

// Packed constants built once per thread.
struct Consts {
    f2 eps30, one2, m1, two2;
    f2 dt2;                      // +dt both lanes (drift)
    f2 pdt2;                     // +dt (interior kick, pairs with nu)
    f2 phdt2;                    // +dt/2 (half kick, pairs with nu)
};

__device__ __forceinline__ void kick2(StateP& t, f2 cf) {
    t.px = fma2(cf, t.qx, t.px);
    t.py = fma2(cf, t.qy, t.py);
    t.pz = fma2(cf, t.qz, t.pz);
}
__device__ __forceinline__ void drift2(StateP& t, f2 dtp) {
    t.qx = fma2(dtp, t.px, t.qx);
    t.qy = fma2(dtp, t.py, t.qy);
    t.qz = fma2(dtp, t.pz, t.qz);
}

// Force eval + kick; cpos = +dt (interior) or +dt/2 (half kick).
// 2 scalar MUFU + ~16 packed FP per thread-step (covers both trajectories).
__device__ __forceinline__ void force_kick2(StateP& t, f2 cpos, const Consts& K) {
    f2 s = fma2(t.qx, t.qx, fma2(t.qy, t.qy, fma2(t.qz, t.qz, K.eps30)));
    float s0, s1; unpack2(s, s0, s1);          // free: register pair
    f2 u  = pack2(rsqrt_approx(s0), rsqrt_approx(s1));   // 2 MUFU + 1 mov
    f2 nu = mul2(u, K.m1);                     // -u
    f2 nh = fma2(s, nu, K.m1);                 // -(1 + r),  r = s*u
    f2 cu = mul2(cpos, nu);                    // c*u with c = -cpos
    f2 g  = t.g;                               // seed: previous 1/(1+r)
    g = mul2(g, fma2(nh, g, K.two2));          // Newton 1: g*(2 - h*g)
    g = mul2(g, fma2(nh, g, K.two2));          // Newton 2
    t.g = g;
    kick2(t, mul2(cu, mul2(g, g)));            // cf = c*u*g^2
}

__global__ void __launch_bounds__(64)
stream_integrate_kernel(const float* __restrict__ ts,
                        const float* __restrict__ w_lead,
                        const float* __restrict__ w_trail,
                        const int*   __restrict__ n_steps_p,
                        float* __restrict__ out,
                        int n) {
    int i = blockIdx.x * blockDim.x + threadIdx.x;
    if (i >= n) return;

    const float2* str = reinterpret_cast<const float2*>(w_trail + (size_t)i * 6);
    const float2* sld = reinterpret_cast<const float2*>(w_lead  + (size_t)i * 6);
    float2 t0 = str[0], t1 = str[1], t2 = str[2];
    float2 l0 = sld[0], l1 = sld[1], l2 = sld[2];

    StateP st;
    st.qx = pack2(t0.x, l0.x);
    st.qy = pack2(t0.y, l0.y);
    st.qz = pack2(t1.x, l1.x);
    st.px = pack2(t1.y, l1.y);
    st.py = pack2(t2.x, l2.x);
    st.pz = pack2(t2.y, l2.y);

    float t_f = __ldg(ts + (n - 1)) + 0.001f;
    int   nst = *n_steps_p;
    float dt  = (t_f - ts[i]) / (float)nst;    // one division for both lanes
    float hdt = 0.5f * dt;

    Consts K;
    K.eps30 = pack2(1e-30f, 1e-30f);
    K.one2  = pack2(1.0f, 1.0f);
    K.m1    = pack2(-1.0f, -1.0f);
    K.two2  = pack2(2.0f, 2.0f);
    K.dt2   = pack2(dt, dt);
    K.pdt2  = pack2(dt, dt);
    K.phdt2 = pack2(hdt, hdt);

    // Opening half kick: seed g per lane with MUFU rcp + one Newton polish.
    {
        f2 s = fma2(st.qx, st.qx, fma2(st.qy, st.qy, fma2(st.qz, st.qz, K.eps30)));
        float s0, s1; unpack2(s, s0, s1);
        f2 u  = pack2(rsqrt_approx(s0), rsqrt_approx(s1));
        f2 nu = mul2(u, K.m1);
        f2 nh = fma2(s, nu, K.m1);             // -(1+r)
        float h0, h1; unpack2(nh, h0, h1);
        f2 g = pack2(rcp_approx(-h0), rcp_approx(-h1));
        g = mul2(g, fma2(nh, g, K.two2));      // polish to ~1 ulp
        st.g = g;
        f2 cu = mul2(K.phdt2, nu);             // (-dt/2)*u
        kick2(st, mul2(cu, mul2(g, g)));
    }

    if (nst == 64) {
        #pragma unroll 7
        for (int k = 0; k < 63; ++k) {
            drift2(st, K.dt2);
            force_kick2(st, K.pdt2, K);
        }
    } else {
        for (int k = 0; k < nst - 1; ++k) {
            drift2(st, K.dt2);
            force_kick2(st, K.pdt2, K);
        }
    }

    // Closing step: drift + half kick.
    drift2(st, K.dt2);
    force_kick2(st, K.phdt2, K);

    // lane lo = trail -> row 2i, lane hi = lead -> row 2i+1 (12 contiguous floats).
    float tqx, lqx, tqy, lqy, tqz, lqz, tpx, lpx, tpy, lpy, tpz, lpz;
    unpack2(st.qx, tqx, lqx); unpack2(st.qy, tqy, lqy); unpack2(st.qz, tqz, lqz);
    unpack2(st.px, tpx, lpx); unpack2(st.py, tpy, lpy); unpack2(st.pz, tpz, lpz);

    float4* dst = reinterpret_cast<float4*>(out + (size_t)i * 12);
    dst[0] = make_float4(tqx, tqy, tqz, tpx);
    dst[1] = make_float4(tpy, tpz, lqx, lqy);
    dst[2] = make_float4(lqz, lpx, lpy, lpz);
}

extern "C" void kernel_launch(void* const* d_in, const int* in_sizes, int n_in,
                              void* d_out, int out_size) {
    const float* ts      = (const float*)d_in[0];
    const float* w_lead  = (const float*)d_in[1];
    const float* w_trail = (const float*)d_in[2];
    const int*   n_steps = (const int*)d_in[3];
    float*       out     = (float*)d_out;

    int n = in_sizes[0];                 // 65536 particles
    int block = 64;                      // 1024 CTAs
    int grid = (n + block - 1) / block;
    stream_integrate_kernel<<<grid, block>>>(ts, w_lead, w_trail, n_steps, out, n);
}